// round 14
// baseline (speedup 1.0000x reference)
#include <cuda_runtime.h>
#include <cuda_bf16.h>
#include <cstdint>

// Problem constants
#define Bb 4
#define Tt 4096
#define Cc 1024
#define Hh 64
#define KPAD 68    // proj X / attn K smem stride (words); 272B row = 16B-mult
#define VPAD 72    // attn V smem stride (words); 288B row = 16B-mult
#define WPAD 200   // proj W smem stride (words)
#define NCHUNK 8   // attn key-tiles per split chunk (512 keys)
#define LOG2E 1.44269504088896f
// pre-scale so HW tf32 truncation of k/v becomes zero-centered (rna-equivalent)
#define TRUNC_COMP 1.00048828125f   // 1 + 2^-11

// Scratch for projected q/k/v (4 MB each)
__device__ float g_q[Bb * Tt * Hh];
__device__ float g_k[Bb * Tt * Hh];
__device__ float g_v[Bb * Tt * Hh];

// Split-K partials: slot = ((b*64+qt)*8 + ci)
__device__ float  g_pO[Bb * 64 * 8][64][Hh];     // 32 MB
__device__ float2 g_pml[Bb * 64 * 8][64];        // (m_log2, l)

__device__ __forceinline__ uint32_t f2tf(float f) {
    uint32_t u; asm("cvt.rna.tf32.f32 %0, %1;" : "=r"(u) : "f"(f)); return u;
}
__device__ __forceinline__ float ex2(float f) {
    float r; asm("ex2.approx.f32 %0, %1;" : "=f"(r) : "f"(f)); return r;
}
__device__ __forceinline__ void cpa16(uint32_t dst, const void* src) {
    asm volatile("cp.async.ca.shared.global [%0], [%1], 16;" :: "r"(dst), "l"(src));
}
#define CP_COMMIT() asm volatile("cp.async.commit_group;")
#define CP_WAIT0()  asm volatile("cp.async.wait_group 0;")

__device__ __forceinline__ void mma_tf32(float* d, const uint32_t* a,
                                         uint32_t b0, uint32_t b1) {
    asm volatile(
        "mma.sync.aligned.m16n8k8.row.col.f32.tf32.tf32.f32 "
        "{%0,%1,%2,%3}, {%4,%5,%6,%7}, {%8,%9}, {%0,%1,%2,%3};"
        : "+f"(d[0]), "+f"(d[1]), "+f"(d[2]), "+f"(d[3])
        : "r"(a[0]), "r"(a[1]), "r"(a[2]), "r"(a[3]), "r"(b0), "r"(b1));
}

// ---------------------------------------------------------------------------
// Kernel 1: fused QKV projection via tf32 mma (PROTECTED structure, ~58us).
// k/v pre-scaled by (1+2^-11) for centered raw-bits truncation downstream;
// q folds 0.125*log2(e).
// ---------------------------------------------------------------------------
__global__ __launch_bounds__(128, 3) void proj_kernel(
    const float* __restrict__ x,
    const float* __restrict__ wk,
    const float* __restrict__ wq,
    const float* __restrict__ wv)
{
    extern __shared__ uint32_t smp[];
    uint32_t* Xs = smp;                 // [m][c] tf32, stride KPAD
    uint32_t* Ws = smp + 64 * KPAD;     // [c][z*64+h] tf32, stride WPAD

    const int m0 = blockIdx.x * 64;
    const int tid = threadIdx.x;
    const int wid = tid >> 5;
    const int lane = tid & 31;
    const int gid = lane >> 2;
    const int tig = lane & 3;
    const int lc = tid & 15;
    const int lr = tid >> 4;

    float o[6][4][4];
    #pragma unroll
    for (int nt = 0; nt < 6; nt++)
        #pragma unroll
        for (int rb = 0; rb < 4; rb++)
            #pragma unroll
            for (int j = 0; j < 4; j++) o[nt][rb][j] = 0.f;

    for (int k0 = 0; k0 < Cc; k0 += 64) {
        #pragma unroll
        for (int p = 0; p < 8; p++) {
            const int row = p * 8 + lr;
            float4 xv = *(const float4*)&x[(size_t)(m0 + row) * Cc + k0 + lc * 4];
            uint32_t* xd = &Xs[row * KPAD + lc * 4];
            xd[0] = f2tf(xv.x); xd[1] = f2tf(xv.y); xd[2] = f2tf(xv.z); xd[3] = f2tf(xv.w);
        }
        #pragma unroll
        for (int z = 0; z < 3; z++) {
            const float* __restrict__ w = (z == 0) ? wk : ((z == 1) ? wq : wv);
            #pragma unroll
            for (int p = 0; p < 8; p++) {
                const int row = p * 8 + lr;
                float4 wv4 = *(const float4*)&w[(size_t)(k0 + row) * Hh + lc * 4];
                uint32_t* wd = &Ws[row * WPAD + z * 64 + lc * 4];
                wd[0] = f2tf(wv4.x); wd[1] = f2tf(wv4.y); wd[2] = f2tf(wv4.z); wd[3] = f2tf(wv4.w);
            }
        }
        __syncthreads();

        #pragma unroll
        for (int s8 = 0; s8 < 8; s8++) {
            uint32_t a[4][4];
            #pragma unroll
            for (int rb = 0; rb < 4; rb++) {
                const int ar = rb * 16 + gid;
                a[rb][0] = Xs[(ar    ) * KPAD + s8 * 8 + tig    ];
                a[rb][1] = Xs[(ar + 8) * KPAD + s8 * 8 + tig    ];
                a[rb][2] = Xs[(ar    ) * KPAD + s8 * 8 + tig + 4];
                a[rb][3] = Xs[(ar + 8) * KPAD + s8 * 8 + tig + 4];
            }
            #pragma unroll
            for (int nt = 0; nt < 6; nt++) {
                const int ntp = wid * 6 + nt;
                uint32_t b0 = Ws[(s8 * 8 + tig    ) * WPAD + ntp * 8 + gid];
                uint32_t b1 = Ws[(s8 * 8 + tig + 4) * WPAD + ntp * 8 + gid];
                #pragma unroll
                for (int rb = 0; rb < 4; rb++)
                    mma_tf32(o[nt][rb], a[rb], b0, b1);
            }
        }
        __syncthreads();
    }

    #pragma unroll
    for (int nt = 0; nt < 6; nt++) {
        const int ntp = wid * 6 + nt;
        const int z = ntp >> 3;
        float* __restrict__ outp = (z == 0) ? g_k : ((z == 1) ? g_q : g_v);
        const float scale = (z == 1) ? (0.125f * LOG2E) : TRUNC_COMP;
        const int hc = (ntp & 7) * 8 + tig * 2;
        #pragma unroll
        for (int rb = 0; rb < 4; rb++) {
            const int mr = m0 + rb * 16 + gid;
            *(float2*)&outp[(size_t)(mr    ) * Hh + hc] =
                make_float2(o[nt][rb][0] * scale, o[nt][rb][1] * scale);
            *(float2*)&outp[(size_t)(mr + 8) * Hh + hc] =
                make_float2(o[nt][rb][2] * scale, o[nt][rb][3] * scale);
        }
    }
}

// ---------------------------------------------------------------------------
// Kernel 2: split-K causal flash attention.
// OCCUPANCY 4 (16 warps/SM): single-buffered cp.async raw K/V (35.8 KB),
// bias+mask folded into the S accumulator init (saves ~32 regs), log2
// softmax, deferred l, raw-bits P and K/V.
// ---------------------------------------------------------------------------
__global__ __launch_bounds__(128, 4) void attn_kernel(
    const float* __restrict__ bias,
    float* __restrict__ outp)
{
    extern __shared__ uint32_t smu[];
    uint32_t* Ks = smu;                 // [key][h] raw f32 bits, stride KPAD
    uint32_t* Vs = smu + 64 * KPAD;     // [slot][h] raw f32 bits, stride VPAD

    const int b = blockIdx.x & 3;
    const int u = blockIdx.x >> 2;      // 0..287
    int ci = 0;
    #pragma unroll
    for (int c = 7; c >= 1; c--) {
        if (u >= 68 * c - 4 * c * c) { ci = c; break; }
    }
    const int qt = 8 * ci + (u - (68 * ci - 4 * ci * ci));
    const int nch = (qt >> 3) + 1;

    const int q0 = qt * 64;
    const int t0 = ci * NCHUNK;
    const int t1 = min(t0 + NCHUNK, qt + 1);

    const int tid = threadIdx.x;
    const int wid = tid >> 5;
    const int lane = tid & 31;
    const int gid = lane >> 2;
    const int tig = lane & 3;
    const int lc = tid & 15;
    const int lr = tid >> 4;

    const float* __restrict__ qbase = g_q + (size_t)b * Tt * Hh;
    const float* __restrict__ kbase = g_k + (size_t)b * Tt * Hh;
    const float* __restrict__ vbase = g_v + (size_t)b * Tt * Hh;

    const uint32_t sbase = (uint32_t)__cvta_generic_to_shared(smu);

    auto load_tile = [&](int t) {
        const int k0 = t * 64;
        const uint32_t vs = sbase + 64u * KPAD * 4u;
        #pragma unroll
        for (int p = 0; p < 8; p++) {
            const int row = p * 8 + lr;
            const int r7 = row & 7;
            const int srow = (row & ~7) | ((r7 & 1) ? ((r7 >> 1) + 4) : (r7 >> 1));
            cpa16(sbase + (uint32_t)(row * KPAD + lc * 4) * 4u,
                  &kbase[(size_t)(k0 + row) * Hh + lc * 4]);
            cpa16(vs + (uint32_t)(srow * VPAD + lc * 4) * 4u,
                  &vbase[(size_t)(k0 + row) * Hh + lc * 4]);
        }
    };

    const int qr0 = q0 + wid * 16 + gid;
    uint32_t qa[8][4];
    #pragma unroll
    for (int s8 = 0; s8 < 8; s8++) {
        qa[s8][0] = f2tf(qbase[(size_t)(qr0    ) * Hh + s8 * 8 + tig    ]);
        qa[s8][1] = f2tf(qbase[(size_t)(qr0 + 8) * Hh + s8 * 8 + tig    ]);
        qa[s8][2] = f2tf(qbase[(size_t)(qr0    ) * Hh + s8 * 8 + tig + 4]);
        qa[s8][3] = f2tf(qbase[(size_t)(qr0 + 8) * Hh + s8 * 8 + tig + 4]);
    }

    float o[8][4];
    #pragma unroll
    for (int nt = 0; nt < 8; nt++)
        #pragma unroll
        for (int j = 0; j < 4; j++) o[nt][j] = 0.f;
    float m0r = -1e30f, m1r = -1e30f, l0 = 0.f, l1 = 0.f;  // l per-lane partial

    for (int t = t0; t < t1; t++) {
        const int k0 = t * 64;

        load_tile(t);
        CP_COMMIT();
        CP_WAIT0();
        __syncthreads();     // tile t visible to all warps

        // --- S init = bias*log2e, with causal mask folded in (exact:
        //     mma accumulates into f32; -1e30 absorbs the QK contribution)
        const bool diag = (t == qt);
        float s[8][4];
        #pragma unroll
        for (int nt = 0; nt < 8; nt++) {
            const int c0 = k0 + nt * 8 + tig * 2;
            float2 bz0 = *(const float2*)&bias[(size_t)(qr0    ) * Tt + c0];
            float2 bz1 = *(const float2*)&bias[(size_t)(qr0 + 8) * Tt + c0];
            s[nt][0] = (diag && c0     > qr0    ) ? -1e30f : bz0.x * LOG2E;
            s[nt][1] = (diag && c0 + 1 > qr0    ) ? -1e30f : bz0.y * LOG2E;
            s[nt][2] = (diag && c0     > qr0 + 8) ? -1e30f : bz1.x * LOG2E;
            s[nt][3] = (diag && c0 + 1 > qr0 + 8) ? -1e30f : bz1.y * LOG2E;
        }

        // --- S += Q K^T ---  (K raw bits; truncation centered by prescale)
        #pragma unroll
        for (int nt = 0; nt < 8; nt++) {
            const uint32_t* krow = &Ks[(nt * 8 + gid) * KPAD];
            #pragma unroll
            for (int s8 = 0; s8 < 8; s8++) {
                uint32_t b0 = krow[s8 * 8 + tig    ];
                uint32_t b1 = krow[s8 * 8 + tig + 4];
                mma_tf32(s[nt], qa[s8], b0, b1);
            }
        }

        // --- online softmax (base-2); only the max is shuffled per tile ---
        float mx0 = -1e30f, mx1 = -1e30f;
        #pragma unroll
        for (int nt = 0; nt < 8; nt++) {
            mx0 = fmaxf(mx0, fmaxf(s[nt][0], s[nt][1]));
            mx1 = fmaxf(mx1, fmaxf(s[nt][2], s[nt][3]));
        }
        mx0 = fmaxf(mx0, __shfl_xor_sync(0xffffffffu, mx0, 1));
        mx0 = fmaxf(mx0, __shfl_xor_sync(0xffffffffu, mx0, 2));
        mx1 = fmaxf(mx1, __shfl_xor_sync(0xffffffffu, mx1, 1));
        mx1 = fmaxf(mx1, __shfl_xor_sync(0xffffffffu, mx1, 2));

        const float mn0 = fmaxf(m0r, mx0);
        const float mn1 = fmaxf(m1r, mx1);
        const float cr0 = ex2(m0r - mn0);
        const float cr1 = ex2(m1r - mn1);
        m0r = mn0; m1r = mn1;

        float rs0 = 0.f, rs1 = 0.f;
        #pragma unroll
        for (int nt = 0; nt < 8; nt++) {
            s[nt][0] = ex2(s[nt][0] - mn0);
            s[nt][1] = ex2(s[nt][1] - mn0);
            s[nt][2] = ex2(s[nt][2] - mn1);
            s[nt][3] = ex2(s[nt][3] - mn1);
            rs0 += s[nt][0] + s[nt][1];
            rs1 += s[nt][2] + s[nt][3];
        }
        l0 = l0 * cr0 + rs0;
        l1 = l1 * cr1 + rs1;

        #pragma unroll
        for (int nt = 0; nt < 8; nt++) {
            o[nt][0] *= cr0; o[nt][1] *= cr0;
            o[nt][2] *= cr1; o[nt][3] *= cr1;
        }

        // --- O += P V (P and V as raw f32 bits) ---
        #pragma unroll
        for (int c8 = 0; c8 < 8; c8++) {
            uint32_t pa[4];
            pa[0] = __float_as_uint(s[c8][0]);
            pa[1] = __float_as_uint(s[c8][2]);
            pa[2] = __float_as_uint(s[c8][1]);
            pa[3] = __float_as_uint(s[c8][3]);
            const uint32_t* vrow0 = &Vs[(c8 * 8 + tig    ) * VPAD];
            const uint32_t* vrow1 = &Vs[(c8 * 8 + tig + 4) * VPAD];
            #pragma unroll
            for (int nt = 0; nt < 8; nt++) {
                uint32_t b0 = vrow0[nt * 8 + gid];
                uint32_t b1 = vrow1[nt * 8 + gid];
                mma_tf32(o[nt], pa, b0, b1);
            }
        }
        __syncthreads();     // compute done before next tile overwrites
    }

    // final l reduction across the 4 lanes of each row group
    l0 += __shfl_xor_sync(0xffffffffu, l0, 1);
    l0 += __shfl_xor_sync(0xffffffffu, l0, 2);
    l1 += __shfl_xor_sync(0xffffffffu, l1, 1);
    l1 += __shfl_xor_sync(0xffffffffu, l1, 2);

    if (nch == 1) {
        const float inv0 = 1.0f / l0;
        const float inv1 = 1.0f / l1;
        float* orow0 = &outp[((size_t)b * Tt + qr0    ) * Hh];
        float* orow1 = &outp[((size_t)b * Tt + qr0 + 8) * Hh];
        #pragma unroll
        for (int nt = 0; nt < 8; nt++) {
            *(float2*)&orow0[nt * 8 + tig * 2] =
                make_float2(o[nt][0] * inv0, o[nt][1] * inv0);
            *(float2*)&orow1[nt * 8 + tig * 2] =
                make_float2(o[nt][2] * inv1, o[nt][3] * inv1);
        }
    } else {
        const int slot = (b * 64 + qt) * 8 + ci;
        const int r0 = wid * 16 + gid;
        float* prow0 = g_pO[slot][r0];
        float* prow1 = g_pO[slot][r0 + 8];
        #pragma unroll
        for (int nt = 0; nt < 8; nt++) {
            *(float2*)&prow0[nt * 8 + tig * 2] = make_float2(o[nt][0], o[nt][1]);
            *(float2*)&prow1[nt * 8 + tig * 2] = make_float2(o[nt][2], o[nt][3]);
        }
        if (tig == 0) {
            g_pml[slot][r0    ] = make_float2(m0r, l0);
            g_pml[slot][r0 + 8] = make_float2(m1r, l1);
        }
    }
}

// ---------------------------------------------------------------------------
// Kernel 3: merge split-K partials for qt >= 8 (up to 8 chunks, log2-domain m).
// ---------------------------------------------------------------------------
__global__ __launch_bounds__(256) void reduce_kernel(float* __restrict__ outp)
{
    const int b  = blockIdx.x / 56;
    const int qt = 8 + blockIdx.x % 56;
    const int nch = (qt >> 3) + 1;        // 2..8
    const int row = threadIdx.x >> 2;
    const int seg = threadIdx.x & 3;
    const int slot0 = (b * 64 + qt) * 8;

    float m[8], w[8];
    float M = -1e30f;
    #pragma unroll
    for (int i = 0; i < 8; i++) {
        if (i < nch) { m[i] = g_pml[slot0 + i][row].x; M = fmaxf(M, m[i]); }
    }
    float L = 0.f;
    #pragma unroll
    for (int i = 0; i < 8; i++) {
        if (i < nch) {
            w[i] = ex2(m[i] - M);
            L += w[i] * g_pml[slot0 + i][row].y;
        }
    }
    const float inv = 1.0f / L;

    float* orow = &outp[((size_t)b * Tt + qt * 64 + row) * Hh + seg * 16];
    #pragma unroll
    for (int g4 = 0; g4 < 4; g4++) {
        float4 acc = make_float4(0.f, 0.f, 0.f, 0.f);
        #pragma unroll
        for (int i = 0; i < 8; i++) {
            if (i < nch) {
                float4 pv = *(const float4*)&g_pO[slot0 + i][row][seg * 16 + g4 * 4];
                acc.x += w[i] * pv.x; acc.y += w[i] * pv.y;
                acc.z += w[i] * pv.z; acc.w += w[i] * pv.w;
            }
        }
        acc.x *= inv; acc.y *= inv; acc.z *= inv; acc.w *= inv;
        *(float4*)&orow[g4 * 4] = acc;
    }
}

// ---------------------------------------------------------------------------
extern "C" void kernel_launch(void* const* d_in, const int* in_sizes, int n_in,
                              void* d_out, int out_size)
{
    const float* x    = (const float*)d_in[0];
    const float* bias = (const float*)d_in[1];
    const float* wk   = (const float*)d_in[2];
    const float* wq   = (const float*)d_in[3];
    const float* wv   = (const float*)d_in[4];
    float* out = (float*)d_out;

    const int psmem = (64 * KPAD + 64 * WPAD) * 4;   // 68608 B
    cudaFuncSetAttribute(proj_kernel,
                         cudaFuncAttributeMaxDynamicSharedMemorySize, psmem);
    proj_kernel<<<Bb * Tt / 64, 128, psmem>>>(x, wk, wq, wv);

    const int asmem = (64 * KPAD + 64 * VPAD) * 4;   // 35840 B (occ 4)
    cudaFuncSetAttribute(attn_kernel,
                         cudaFuncAttributeMaxDynamicSharedMemorySize, asmem);
    attn_kernel<<<4 * 288, 128, asmem>>>(bias, out);

    reduce_kernel<<<Bb * 56, 256>>>(out);
}

// round 15
// speedup vs baseline: 1.1717x; 1.1717x over previous
#include <cuda_runtime.h>
#include <cuda_bf16.h>
#include <cstdint>

// Problem constants
#define Bb 4
#define Tt 4096
#define Cc 1024
#define Hh 64
#define KPAD 68    // proj X / attn K smem stride (words); 272B row = 16B-mult
#define VPAD 72    // attn V smem stride (words); 288B row = 16B-mult
#define WPAD 200   // proj W smem stride (words)
#define NCHUNK 8   // attn key-tiles per split chunk (512 keys)
#define LOG2E 1.44269504088896f
#define TRUNC_COMP 1.00048828125f   // 1 + 2^-11 (centers raw-bits truncation)

// Scratch for projected q/k/v (4 MB each)
__device__ float g_q[Bb * Tt * Hh];
__device__ float g_k[Bb * Tt * Hh];
__device__ float g_v[Bb * Tt * Hh];

// Split-K partials: slot = ((b*64+qt)*8 + ci)
__device__ float  g_pO[Bb * 64 * 8][64][Hh];     // 32 MB
__device__ float2 g_pml[Bb * 64 * 8][64];        // (m_log2, l)

__device__ __forceinline__ uint32_t f2tf(float f) {
    uint32_t u; asm("cvt.rna.tf32.f32 %0, %1;" : "=r"(u) : "f"(f)); return u;
}
__device__ __forceinline__ float ex2(float f) {
    float r; asm("ex2.approx.f32 %0, %1;" : "=f"(r) : "f"(f)); return r;
}
__device__ __forceinline__ void cpa16(uint32_t dst, const void* src) {
    asm volatile("cp.async.ca.shared.global [%0], [%1], 16;" :: "r"(dst), "l"(src));
}
#define CP_COMMIT() asm volatile("cp.async.commit_group;")
#define CP_WAIT0()  asm volatile("cp.async.wait_group 0;")

__device__ __forceinline__ void mma_tf32(float* d, const uint32_t* a,
                                         uint32_t b0, uint32_t b1) {
    asm volatile(
        "mma.sync.aligned.m16n8k8.row.col.f32.tf32.tf32.f32 "
        "{%0,%1,%2,%3}, {%4,%5,%6,%7}, {%8,%9}, {%0,%1,%2,%3};"
        : "+f"(d[0]), "+f"(d[1]), "+f"(d[2]), "+f"(d[3])
        : "r"(a[0]), "r"(a[1]), "r"(a[2]), "r"(a[3]), "r"(b0), "r"(b1));
}

// ---------------------------------------------------------------------------
// Kernel 0: zero q/k/v accumulators (proj halves atomicAdd into them).
// ---------------------------------------------------------------------------
__global__ __launch_bounds__(256) void zero_kernel()
{
    const size_t i = ((size_t)blockIdx.x * 256 + threadIdx.x) * 4;
    const float4 z = make_float4(0.f, 0.f, 0.f, 0.f);
    *(float4*)&g_q[i] = z;
    *(float4*)&g_k[i] = z;
    *(float4*)&g_v[i] = z;
}

// ---------------------------------------------------------------------------
// Kernel 1: fused QKV projection via tf32 mma — split-K over C.
// grid (256, 2): blockIdx.y picks the 512-deep K half; partials REDG-added.
// Inner structure = PROTECTED R5/R12 version (cvt-at-store, warp covers
// all 4 row-blocks x 6 n-tiles).
// ---------------------------------------------------------------------------
__global__ __launch_bounds__(128, 3) void proj_kernel(
    const float* __restrict__ x,
    const float* __restrict__ wk,
    const float* __restrict__ wq,
    const float* __restrict__ wv)
{
    extern __shared__ uint32_t smp[];
    uint32_t* Xs = smp;                 // [m][c] tf32, stride KPAD
    uint32_t* Ws = smp + 64 * KPAD;     // [c][z*64+h] tf32, stride WPAD

    const int m0 = blockIdx.x * 64;
    const int kk = blockIdx.y;          // 0 or 1: which 512-deep K half
    const int tid = threadIdx.x;
    const int wid = tid >> 5;
    const int lane = tid & 31;
    const int gid = lane >> 2;
    const int tig = lane & 3;
    const int lc = tid & 15;
    const int lr = tid >> 4;

    float o[6][4][4];
    #pragma unroll
    for (int nt = 0; nt < 6; nt++)
        #pragma unroll
        for (int rb = 0; rb < 4; rb++)
            #pragma unroll
            for (int j = 0; j < 4; j++) o[nt][rb][j] = 0.f;

    const int kbeg = kk * (Cc / 2);
    for (int k0 = kbeg; k0 < kbeg + Cc / 2; k0 += 64) {
        #pragma unroll
        for (int p = 0; p < 8; p++) {
            const int row = p * 8 + lr;
            float4 xv = *(const float4*)&x[(size_t)(m0 + row) * Cc + k0 + lc * 4];
            uint32_t* xd = &Xs[row * KPAD + lc * 4];
            xd[0] = f2tf(xv.x); xd[1] = f2tf(xv.y); xd[2] = f2tf(xv.z); xd[3] = f2tf(xv.w);
        }
        #pragma unroll
        for (int z = 0; z < 3; z++) {
            const float* __restrict__ w = (z == 0) ? wk : ((z == 1) ? wq : wv);
            #pragma unroll
            for (int p = 0; p < 8; p++) {
                const int row = p * 8 + lr;
                float4 wv4 = *(const float4*)&w[(size_t)(k0 + row) * Hh + lc * 4];
                uint32_t* wd = &Ws[row * WPAD + z * 64 + lc * 4];
                wd[0] = f2tf(wv4.x); wd[1] = f2tf(wv4.y); wd[2] = f2tf(wv4.z); wd[3] = f2tf(wv4.w);
            }
        }
        __syncthreads();

        #pragma unroll
        for (int s8 = 0; s8 < 8; s8++) {
            uint32_t a[4][4];
            #pragma unroll
            for (int rb = 0; rb < 4; rb++) {
                const int ar = rb * 16 + gid;
                a[rb][0] = Xs[(ar    ) * KPAD + s8 * 8 + tig    ];
                a[rb][1] = Xs[(ar + 8) * KPAD + s8 * 8 + tig    ];
                a[rb][2] = Xs[(ar    ) * KPAD + s8 * 8 + tig + 4];
                a[rb][3] = Xs[(ar + 8) * KPAD + s8 * 8 + tig + 4];
            }
            #pragma unroll
            for (int nt = 0; nt < 6; nt++) {
                const int ntp = wid * 6 + nt;
                uint32_t b0 = Ws[(s8 * 8 + tig    ) * WPAD + ntp * 8 + gid];
                uint32_t b1 = Ws[(s8 * 8 + tig + 4) * WPAD + ntp * 8 + gid];
                #pragma unroll
                for (int rb = 0; rb < 4; rb++)
                    mma_tf32(o[nt][rb], a[rb], b0, b1);
            }
        }
        __syncthreads();
    }

    #pragma unroll
    for (int nt = 0; nt < 6; nt++) {
        const int ntp = wid * 6 + nt;
        const int z = ntp >> 3;
        float* __restrict__ outp = (z == 0) ? g_k : ((z == 1) ? g_q : g_v);
        const float scale = (z == 1) ? (0.125f * LOG2E) : TRUNC_COMP;
        const int hc = (ntp & 7) * 8 + tig * 2;
        #pragma unroll
        for (int rb = 0; rb < 4; rb++) {
            const int mr = m0 + rb * 16 + gid;
            atomicAdd(&outp[(size_t)(mr    ) * Hh + hc    ], o[nt][rb][0] * scale);
            atomicAdd(&outp[(size_t)(mr    ) * Hh + hc + 1], o[nt][rb][1] * scale);
            atomicAdd(&outp[(size_t)(mr + 8) * Hh + hc    ], o[nt][rb][2] * scale);
            atomicAdd(&outp[(size_t)(mr + 8) * Hh + hc + 1], o[nt][rb][3] * scale);
        }
    }
}

// ---------------------------------------------------------------------------
// Kernel 2: split-K causal flash attention — R12 config (measured best):
// double-buffered cp.async raw K/V, occ 3, log2 softmax, deferred l,
// raw-bits P/K/V.  Plus register-cheap bias+mask fold into S init.
// ---------------------------------------------------------------------------
__global__ __launch_bounds__(128, 3) void attn_kernel(
    const float* __restrict__ bias,
    float* __restrict__ outp)
{
    extern __shared__ uint32_t smu[];
    const int ASTG = 64 * KPAD + 64 * VPAD;   // 8960 words per stage

    const int b = blockIdx.x & 3;
    const int u = blockIdx.x >> 2;      // 0..287
    int ci = 0;
    #pragma unroll
    for (int c = 7; c >= 1; c--) {
        if (u >= 68 * c - 4 * c * c) { ci = c; break; }
    }
    const int qt = 8 * ci + (u - (68 * ci - 4 * ci * ci));
    const int nch = (qt >> 3) + 1;

    const int q0 = qt * 64;
    const int t0 = ci * NCHUNK;
    const int t1 = min(t0 + NCHUNK, qt + 1);

    const int tid = threadIdx.x;
    const int wid = tid >> 5;
    const int lane = tid & 31;
    const int gid = lane >> 2;
    const int tig = lane & 3;
    const int lc = tid & 15;
    const int lr = tid >> 4;

    const float* __restrict__ qbase = g_q + (size_t)b * Tt * Hh;
    const float* __restrict__ kbase = g_k + (size_t)b * Tt * Hh;
    const float* __restrict__ vbase = g_v + (size_t)b * Tt * Hh;

    const uint32_t sbase = (uint32_t)__cvta_generic_to_shared(smu);

    auto load_tile = [&](int t, int s) {
        const int k0 = t * 64;
        const uint32_t ks = sbase + (uint32_t)(s * ASTG) * 4u;
        const uint32_t vs = ks + 64u * KPAD * 4u;
        #pragma unroll
        for (int p = 0; p < 8; p++) {
            const int row = p * 8 + lr;
            const int r7 = row & 7;
            const int srow = (row & ~7) | ((r7 & 1) ? ((r7 >> 1) + 4) : (r7 >> 1));
            cpa16(ks + (uint32_t)(row * KPAD + lc * 4) * 4u,
                  &kbase[(size_t)(k0 + row) * Hh + lc * 4]);
            cpa16(vs + (uint32_t)(srow * VPAD + lc * 4) * 4u,
                  &vbase[(size_t)(k0 + row) * Hh + lc * 4]);
        }
    };

    const int qr0 = q0 + wid * 16 + gid;
    uint32_t qa[8][4];
    #pragma unroll
    for (int s8 = 0; s8 < 8; s8++) {
        qa[s8][0] = f2tf(qbase[(size_t)(qr0    ) * Hh + s8 * 8 + tig    ]);
        qa[s8][1] = f2tf(qbase[(size_t)(qr0 + 8) * Hh + s8 * 8 + tig    ]);
        qa[s8][2] = f2tf(qbase[(size_t)(qr0    ) * Hh + s8 * 8 + tig + 4]);
        qa[s8][3] = f2tf(qbase[(size_t)(qr0 + 8) * Hh + s8 * 8 + tig + 4]);
    }

    float o[8][4];
    #pragma unroll
    for (int nt = 0; nt < 8; nt++)
        #pragma unroll
        for (int j = 0; j < 4; j++) o[nt][j] = 0.f;
    float m0r = -1e30f, m1r = -1e30f, l0 = 0.f, l1 = 0.f;  // l per-lane partial

    load_tile(t0, 0);
    CP_COMMIT();

    for (int t = t0; t < t1; t++) {
        const int k0 = t * 64;
        const int cur = (t - t0) & 1;
        CP_WAIT0();
        __syncthreads();     // tile t landed; all warps done with tile t-1
        if (t + 1 < t1) { load_tile(t + 1, cur ^ 1); CP_COMMIT(); }

        const uint32_t* Kf = smu + cur * ASTG;
        const uint32_t* Vf = Kf + 64 * KPAD;

        // --- S init = bias*log2e with causal mask folded (exact; mma
        //     accumulates into f32, -1e30 absorbs the QK contribution) ---
        const bool diag = (t == qt);
        float s[8][4];
        #pragma unroll
        for (int nt = 0; nt < 8; nt++) {
            const int c0 = k0 + nt * 8 + tig * 2;
            float2 bz0 = *(const float2*)&bias[(size_t)(qr0    ) * Tt + c0];
            float2 bz1 = *(const float2*)&bias[(size_t)(qr0 + 8) * Tt + c0];
            s[nt][0] = (diag && c0     > qr0    ) ? -1e30f : bz0.x * LOG2E;
            s[nt][1] = (diag && c0 + 1 > qr0    ) ? -1e30f : bz0.y * LOG2E;
            s[nt][2] = (diag && c0     > qr0 + 8) ? -1e30f : bz1.x * LOG2E;
            s[nt][3] = (diag && c0 + 1 > qr0 + 8) ? -1e30f : bz1.y * LOG2E;
        }

        // --- S += Q K^T ---  (K raw bits; truncation centered by prescale)
        #pragma unroll
        for (int nt = 0; nt < 8; nt++) {
            const uint32_t* krow = &Kf[(nt * 8 + gid) * KPAD];
            #pragma unroll
            for (int s8 = 0; s8 < 8; s8++) {
                uint32_t b0 = krow[s8 * 8 + tig    ];
                uint32_t b1 = krow[s8 * 8 + tig + 4];
                mma_tf32(s[nt], qa[s8], b0, b1);
            }
        }

        // --- online softmax (base-2); only the max is shuffled per tile ---
        float mx0 = -1e30f, mx1 = -1e30f;
        #pragma unroll
        for (int nt = 0; nt < 8; nt++) {
            mx0 = fmaxf(mx0, fmaxf(s[nt][0], s[nt][1]));
            mx1 = fmaxf(mx1, fmaxf(s[nt][2], s[nt][3]));
        }
        mx0 = fmaxf(mx0, __shfl_xor_sync(0xffffffffu, mx0, 1));
        mx0 = fmaxf(mx0, __shfl_xor_sync(0xffffffffu, mx0, 2));
        mx1 = fmaxf(mx1, __shfl_xor_sync(0xffffffffu, mx1, 1));
        mx1 = fmaxf(mx1, __shfl_xor_sync(0xffffffffu, mx1, 2));

        const float mn0 = fmaxf(m0r, mx0);
        const float mn1 = fmaxf(m1r, mx1);
        const float cr0 = ex2(m0r - mn0);
        const float cr1 = ex2(m1r - mn1);
        m0r = mn0; m1r = mn1;

        float rs0 = 0.f, rs1 = 0.f;
        #pragma unroll
        for (int nt = 0; nt < 8; nt++) {
            s[nt][0] = ex2(s[nt][0] - mn0);
            s[nt][1] = ex2(s[nt][1] - mn0);
            s[nt][2] = ex2(s[nt][2] - mn1);
            s[nt][3] = ex2(s[nt][3] - mn1);
            rs0 += s[nt][0] + s[nt][1];
            rs1 += s[nt][2] + s[nt][3];
        }
        l0 = l0 * cr0 + rs0;
        l1 = l1 * cr1 + rs1;

        #pragma unroll
        for (int nt = 0; nt < 8; nt++) {
            o[nt][0] *= cr0; o[nt][1] *= cr0;
            o[nt][2] *= cr1; o[nt][3] *= cr1;
        }

        // --- O += P V (P and V as raw f32 bits) ---
        #pragma unroll
        for (int c8 = 0; c8 < 8; c8++) {
            uint32_t pa[4];
            pa[0] = __float_as_uint(s[c8][0]);
            pa[1] = __float_as_uint(s[c8][2]);
            pa[2] = __float_as_uint(s[c8][1]);
            pa[3] = __float_as_uint(s[c8][3]);
            const uint32_t* vrow0 = &Vf[(c8 * 8 + tig    ) * VPAD];
            const uint32_t* vrow1 = &Vf[(c8 * 8 + tig + 4) * VPAD];
            #pragma unroll
            for (int nt = 0; nt < 8; nt++) {
                uint32_t b0 = vrow0[nt * 8 + gid];
                uint32_t b1 = vrow1[nt * 8 + gid];
                mma_tf32(o[nt], pa, b0, b1);
            }
        }
        // single barrier per tile: next iteration's top barrier orders reuse
    }

    // final l reduction across the 4 lanes of each row group
    l0 += __shfl_xor_sync(0xffffffffu, l0, 1);
    l0 += __shfl_xor_sync(0xffffffffu, l0, 2);
    l1 += __shfl_xor_sync(0xffffffffu, l1, 1);
    l1 += __shfl_xor_sync(0xffffffffu, l1, 2);

    if (nch == 1) {
        const float inv0 = 1.0f / l0;
        const float inv1 = 1.0f / l1;
        float* orow0 = &outp[((size_t)b * Tt + qr0    ) * Hh];
        float* orow1 = &outp[((size_t)b * Tt + qr0 + 8) * Hh];
        #pragma unroll
        for (int nt = 0; nt < 8; nt++) {
            *(float2*)&orow0[nt * 8 + tig * 2] =
                make_float2(o[nt][0] * inv0, o[nt][1] * inv0);
            *(float2*)&orow1[nt * 8 + tig * 2] =
                make_float2(o[nt][2] * inv1, o[nt][3] * inv1);
        }
    } else {
        const int slot = (b * 64 + qt) * 8 + ci;
        const int r0 = wid * 16 + gid;
        float* prow0 = g_pO[slot][r0];
        float* prow1 = g_pO[slot][r0 + 8];
        #pragma unroll
        for (int nt = 0; nt < 8; nt++) {
            *(float2*)&prow0[nt * 8 + tig * 2] = make_float2(o[nt][0], o[nt][1]);
            *(float2*)&prow1[nt * 8 + tig * 2] = make_float2(o[nt][2], o[nt][3]);
        }
        if (tig == 0) {
            g_pml[slot][r0    ] = make_float2(m0r, l0);
            g_pml[slot][r0 + 8] = make_float2(m1r, l1);
        }
    }
}

// ---------------------------------------------------------------------------
// Kernel 3: merge split-K partials for qt >= 8 (up to 8 chunks, log2-domain m).
// ---------------------------------------------------------------------------
__global__ __launch_bounds__(256) void reduce_kernel(float* __restrict__ outp)
{
    const int b  = blockIdx.x / 56;
    const int qt = 8 + blockIdx.x % 56;
    const int nch = (qt >> 3) + 1;        // 2..8
    const int row = threadIdx.x >> 2;
    const int seg = threadIdx.x & 3;
    const int slot0 = (b * 64 + qt) * 8;

    float m[8], w[8];
    float M = -1e30f;
    #pragma unroll
    for (int i = 0; i < 8; i++) {
        if (i < nch) { m[i] = g_pml[slot0 + i][row].x; M = fmaxf(M, m[i]); }
    }
    float L = 0.f;
    #pragma unroll
    for (int i = 0; i < 8; i++) {
        if (i < nch) {
            w[i] = ex2(m[i] - M);
            L += w[i] * g_pml[slot0 + i][row].y;
        }
    }
    const float inv = 1.0f / L;

    float* orow = &outp[((size_t)b * Tt + qt * 64 + row) * Hh + seg * 16];
    #pragma unroll
    for (int g4 = 0; g4 < 4; g4++) {
        float4 acc = make_float4(0.f, 0.f, 0.f, 0.f);
        #pragma unroll
        for (int i = 0; i < 8; i++) {
            if (i < nch) {
                float4 pv = *(const float4*)&g_pO[slot0 + i][row][seg * 16 + g4 * 4];
                acc.x += w[i] * pv.x; acc.y += w[i] * pv.y;
                acc.z += w[i] * pv.z; acc.w += w[i] * pv.w;
            }
        }
        acc.x *= inv; acc.y *= inv; acc.z *= inv; acc.w *= inv;
        *(float4*)&orow[g4 * 4] = acc;
    }
}

// ---------------------------------------------------------------------------
extern "C" void kernel_launch(void* const* d_in, const int* in_sizes, int n_in,
                              void* d_out, int out_size)
{
    const float* x    = (const float*)d_in[0];
    const float* bias = (const float*)d_in[1];
    const float* wk   = (const float*)d_in[2];
    const float* wq   = (const float*)d_in[3];
    const float* wv   = (const float*)d_in[4];
    float* out = (float*)d_out;

    // zero q/k/v accumulators: 1M floats each, 4 float4s per thread-block-row
    zero_kernel<<<Bb * Tt * Hh / (256 * 4), 256>>>();

    const int psmem = (64 * KPAD + 64 * WPAD) * 4;       // 68608 B
    cudaFuncSetAttribute(proj_kernel,
                         cudaFuncAttributeMaxDynamicSharedMemorySize, psmem);
    dim3 gp(Bb * Tt / 64, 2);
    proj_kernel<<<gp, 128, psmem>>>(x, wk, wq, wv);

    const int asmem = 2 * (64 * KPAD + 64 * VPAD) * 4;   // 71680 B
    cudaFuncSetAttribute(attn_kernel,
                         cudaFuncAttributeMaxDynamicSharedMemorySize, asmem);
    attn_kernel<<<4 * 288, 128, asmem>>>(bias, out);

    reduce_kernel<<<Bb * 56, 256>>>(out);
}

// round 17
// speedup vs baseline: 1.4067x; 1.2006x over previous
#include <cuda_runtime.h>
#include <cuda_bf16.h>
#include <cstdint>

// Problem constants
#define Bb 4
#define Tt 4096
#define Cc 1024
#define Hh 64
#define KPAD 68    // proj X / attn K smem stride (words); 272B row = 16B-mult
#define VPAD 72    // attn V smem stride (words); 288B row = 16B-mult
#define WPAD 200   // proj W smem stride (words)
#define NCHUNK 8   // attn key-tiles per split chunk (512 keys)
#define LOG2E 1.44269504088896f
// pre-scale so HW tf32 truncation of k/v becomes zero-centered (rna-equivalent)
#define TRUNC_COMP 1.00048828125f   // 1 + 2^-11

// Scratch for projected q/k/v (4 MB each)
__device__ float g_q[Bb * Tt * Hh];
__device__ float g_k[Bb * Tt * Hh];
__device__ float g_v[Bb * Tt * Hh];

// Split-K partials: slot = ((b*64+qt)*8 + ci)
__device__ float  g_pO[Bb * 64 * 8][64][Hh];     // 32 MB
__device__ float2 g_pml[Bb * 64 * 8][64];        // (m_log2, l)

__device__ __forceinline__ uint32_t f2tf(float f) {
    uint32_t u; asm("cvt.rna.tf32.f32 %0, %1;" : "=r"(u) : "f"(f)); return u;
}
__device__ __forceinline__ float ex2(float f) {
    float r; asm("ex2.approx.f32 %0, %1;" : "=f"(r) : "f"(f)); return r;
}
__device__ __forceinline__ void cpa16(uint32_t dst, const void* src) {
    asm volatile("cp.async.ca.shared.global [%0], [%1], 16;" :: "r"(dst), "l"(src));
}
#define CP_COMMIT() asm volatile("cp.async.commit_group;")
#define CP_WAIT0()  asm volatile("cp.async.wait_group 0;")

__device__ __forceinline__ void mma_tf32(float* d, const uint32_t* a,
                                         uint32_t b0, uint32_t b1) {
    asm volatile(
        "mma.sync.aligned.m16n8k8.row.col.f32.tf32.tf32.f32 "
        "{%0,%1,%2,%3}, {%4,%5,%6,%7}, {%8,%9}, {%0,%1,%2,%3};"
        : "+f"(d[0]), "+f"(d[1]), "+f"(d[2]), "+f"(d[3])
        : "r"(a[0]), "r"(a[1]), "r"(a[2]), "r"(a[3]), "r"(b0), "r"(b1));
}

// ---------------------------------------------------------------------------
// Kernel 1: fused QKV projection via tf32 mma (PROTECTED R12 version).
// k/v pre-scaled by (1+2^-11) for centered raw-bits truncation downstream;
// q folds 0.125*log2(e).  Direct stores (no atomics).
// ---------------------------------------------------------------------------
__global__ __launch_bounds__(128, 3) void proj_kernel(
    const float* __restrict__ x,
    const float* __restrict__ wk,
    const float* __restrict__ wq,
    const float* __restrict__ wv)
{
    extern __shared__ uint32_t smp[];
    uint32_t* Xs = smp;                 // [m][c] tf32, stride KPAD
    uint32_t* Ws = smp + 64 * KPAD;     // [c][z*64+h] tf32, stride WPAD

    const int m0 = blockIdx.x * 64;
    const int tid = threadIdx.x;
    const int wid = tid >> 5;
    const int lane = tid & 31;
    const int gid = lane >> 2;
    const int tig = lane & 3;
    const int lc = tid & 15;
    const int lr = tid >> 4;

    float o[6][4][4];
    #pragma unroll
    for (int nt = 0; nt < 6; nt++)
        #pragma unroll
        for (int rb = 0; rb < 4; rb++)
            #pragma unroll
            for (int j = 0; j < 4; j++) o[nt][rb][j] = 0.f;

    for (int k0 = 0; k0 < Cc; k0 += 64) {
        #pragma unroll
        for (int p = 0; p < 8; p++) {
            const int row = p * 8 + lr;
            float4 xv = *(const float4*)&x[(size_t)(m0 + row) * Cc + k0 + lc * 4];
            uint32_t* xd = &Xs[row * KPAD + lc * 4];
            xd[0] = f2tf(xv.x); xd[1] = f2tf(xv.y); xd[2] = f2tf(xv.z); xd[3] = f2tf(xv.w);
        }
        #pragma unroll
        for (int z = 0; z < 3; z++) {
            const float* __restrict__ w = (z == 0) ? wk : ((z == 1) ? wq : wv);
            #pragma unroll
            for (int p = 0; p < 8; p++) {
                const int row = p * 8 + lr;
                float4 wv4 = *(const float4*)&w[(size_t)(k0 + row) * Hh + lc * 4];
                uint32_t* wd = &Ws[row * WPAD + z * 64 + lc * 4];
                wd[0] = f2tf(wv4.x); wd[1] = f2tf(wv4.y); wd[2] = f2tf(wv4.z); wd[3] = f2tf(wv4.w);
            }
        }
        __syncthreads();

        #pragma unroll
        for (int s8 = 0; s8 < 8; s8++) {
            uint32_t a[4][4];
            #pragma unroll
            for (int rb = 0; rb < 4; rb++) {
                const int ar = rb * 16 + gid;
                a[rb][0] = Xs[(ar    ) * KPAD + s8 * 8 + tig    ];
                a[rb][1] = Xs[(ar + 8) * KPAD + s8 * 8 + tig    ];
                a[rb][2] = Xs[(ar    ) * KPAD + s8 * 8 + tig + 4];
                a[rb][3] = Xs[(ar + 8) * KPAD + s8 * 8 + tig + 4];
            }
            #pragma unroll
            for (int nt = 0; nt < 6; nt++) {
                const int ntp = wid * 6 + nt;
                uint32_t b0 = Ws[(s8 * 8 + tig    ) * WPAD + ntp * 8 + gid];
                uint32_t b1 = Ws[(s8 * 8 + tig + 4) * WPAD + ntp * 8 + gid];
                #pragma unroll
                for (int rb = 0; rb < 4; rb++)
                    mma_tf32(o[nt][rb], a[rb], b0, b1);
            }
        }
        __syncthreads();
    }

    #pragma unroll
    for (int nt = 0; nt < 6; nt++) {
        const int ntp = wid * 6 + nt;
        const int z = ntp >> 3;
        float* __restrict__ outp = (z == 0) ? g_k : ((z == 1) ? g_q : g_v);
        const float scale = (z == 1) ? (0.125f * LOG2E) : TRUNC_COMP;
        const int hc = (ntp & 7) * 8 + tig * 2;
        #pragma unroll
        for (int rb = 0; rb < 4; rb++) {
            const int mr = m0 + rb * 16 + gid;
            *(float2*)&outp[(size_t)(mr    ) * Hh + hc] =
                make_float2(o[nt][rb][0] * scale, o[nt][rb][1] * scale);
            *(float2*)&outp[(size_t)(mr + 8) * Hh + hc] =
                make_float2(o[nt][rb][2] * scale, o[nt][rb][3] * scale);
        }
    }
}

// ---------------------------------------------------------------------------
// Kernel 2: split-K causal flash attention (PROTECTED R12 version).
// cp.async double-buffered RAW K/V; bias prefetched into regs BEFORE the
// QK^T mma loop (latency hidden) and added after; log2 softmax; deferred l;
// raw-bits P/K/V; single barrier per tile.
// ---------------------------------------------------------------------------
__global__ __launch_bounds__(128, 3) void attn_kernel(
    const float* __restrict__ bias,
    float* __restrict__ outp)
{
    extern __shared__ uint32_t smu[];
    const int ASTG = 64 * KPAD + 64 * VPAD;   // 8960 words per stage

    const int b = blockIdx.x & 3;
    const int u = blockIdx.x >> 2;      // 0..287
    int ci = 0;
    #pragma unroll
    for (int c = 7; c >= 1; c--) {
        if (u >= 68 * c - 4 * c * c) { ci = c; break; }
    }
    const int qt = 8 * ci + (u - (68 * ci - 4 * ci * ci));
    const int nch = (qt >> 3) + 1;

    const int q0 = qt * 64;
    const int t0 = ci * NCHUNK;
    const int t1 = min(t0 + NCHUNK, qt + 1);

    const int tid = threadIdx.x;
    const int wid = tid >> 5;
    const int lane = tid & 31;
    const int gid = lane >> 2;
    const int tig = lane & 3;
    const int lc = tid & 15;
    const int lr = tid >> 4;

    const float* __restrict__ qbase = g_q + (size_t)b * Tt * Hh;
    const float* __restrict__ kbase = g_k + (size_t)b * Tt * Hh;
    const float* __restrict__ vbase = g_v + (size_t)b * Tt * Hh;

    const uint32_t sbase = (uint32_t)__cvta_generic_to_shared(smu);

    auto load_tile = [&](int t, int s) {
        const int k0 = t * 64;
        const uint32_t ks = sbase + (uint32_t)(s * ASTG) * 4u;
        const uint32_t vs = ks + 64u * KPAD * 4u;
        #pragma unroll
        for (int p = 0; p < 8; p++) {
            const int row = p * 8 + lr;
            const int r7 = row & 7;
            const int srow = (row & ~7) | ((r7 & 1) ? ((r7 >> 1) + 4) : (r7 >> 1));
            cpa16(ks + (uint32_t)(row * KPAD + lc * 4) * 4u,
                  &kbase[(size_t)(k0 + row) * Hh + lc * 4]);
            cpa16(vs + (uint32_t)(srow * VPAD + lc * 4) * 4u,
                  &vbase[(size_t)(k0 + row) * Hh + lc * 4]);
        }
    };

    const int qr0 = q0 + wid * 16 + gid;
    uint32_t qa[8][4];
    #pragma unroll
    for (int s8 = 0; s8 < 8; s8++) {
        qa[s8][0] = f2tf(qbase[(size_t)(qr0    ) * Hh + s8 * 8 + tig    ]);
        qa[s8][1] = f2tf(qbase[(size_t)(qr0 + 8) * Hh + s8 * 8 + tig    ]);
        qa[s8][2] = f2tf(qbase[(size_t)(qr0    ) * Hh + s8 * 8 + tig + 4]);
        qa[s8][3] = f2tf(qbase[(size_t)(qr0 + 8) * Hh + s8 * 8 + tig + 4]);
    }

    float o[8][4];
    #pragma unroll
    for (int nt = 0; nt < 8; nt++)
        #pragma unroll
        for (int j = 0; j < 4; j++) o[nt][j] = 0.f;
    float m0r = -1e30f, m1r = -1e30f, l0 = 0.f, l1 = 0.f;  // l per-lane partial

    load_tile(t0, 0);
    CP_COMMIT();

    for (int t = t0; t < t1; t++) {
        const int k0 = t * 64;
        const int cur = (t - t0) & 1;
        CP_WAIT0();
        __syncthreads();     // tile t landed; all warps done with tile t-1
        if (t + 1 < t1) { load_tile(t + 1, cur ^ 1); CP_COMMIT(); }

        const uint32_t* Kf = smu + cur * ASTG;
        const uint32_t* Vf = Kf + 64 * KPAD;

        // bias prefetch BEFORE the mma loop — LDG latency overlaps 64 mma
        float2 bz0[8], bz1[8];
        #pragma unroll
        for (int nt = 0; nt < 8; nt++) {
            const int c0 = k0 + nt * 8 + tig * 2;
            bz0[nt] = *(const float2*)&bias[(size_t)(qr0    ) * Tt + c0];
            bz1[nt] = *(const float2*)&bias[(size_t)(qr0 + 8) * Tt + c0];
        }

        // --- S = Q K^T ---  (K raw bits; truncation centered by prescale)
        float s[8][4];
        #pragma unroll
        for (int nt = 0; nt < 8; nt++) {
            #pragma unroll
            for (int j = 0; j < 4; j++) s[nt][j] = 0.f;
            const uint32_t* krow = &Kf[(nt * 8 + gid) * KPAD];
            #pragma unroll
            for (int s8 = 0; s8 < 8; s8++) {
                uint32_t b0 = krow[s8 * 8 + tig    ];
                uint32_t b1 = krow[s8 * 8 + tig + 4];
                mma_tf32(s[nt], qa[s8], b0, b1);
            }
        }

        // --- bias (log2 domain) + causal mask ---
        const bool diag = (t == qt);
        #pragma unroll
        for (int nt = 0; nt < 8; nt++) {
            const int c0 = k0 + nt * 8 + tig * 2;
            s[nt][0] += bz0[nt].x * LOG2E; s[nt][1] += bz0[nt].y * LOG2E;
            s[nt][2] += bz1[nt].x * LOG2E; s[nt][3] += bz1[nt].y * LOG2E;
            if (diag) {
                if (c0     > qr0    ) s[nt][0] = -1e30f;
                if (c0 + 1 > qr0    ) s[nt][1] = -1e30f;
                if (c0     > qr0 + 8) s[nt][2] = -1e30f;
                if (c0 + 1 > qr0 + 8) s[nt][3] = -1e30f;
            }
        }

        // --- online softmax (base-2); only the max is shuffled per tile ---
        float mx0 = -1e30f, mx1 = -1e30f;
        #pragma unroll
        for (int nt = 0; nt < 8; nt++) {
            mx0 = fmaxf(mx0, fmaxf(s[nt][0], s[nt][1]));
            mx1 = fmaxf(mx1, fmaxf(s[nt][2], s[nt][3]));
        }
        mx0 = fmaxf(mx0, __shfl_xor_sync(0xffffffffu, mx0, 1));
        mx0 = fmaxf(mx0, __shfl_xor_sync(0xffffffffu, mx0, 2));
        mx1 = fmaxf(mx1, __shfl_xor_sync(0xffffffffu, mx1, 1));
        mx1 = fmaxf(mx1, __shfl_xor_sync(0xffffffffu, mx1, 2));

        const float mn0 = fmaxf(m0r, mx0);
        const float mn1 = fmaxf(m1r, mx1);
        const float cr0 = ex2(m0r - mn0);
        const float cr1 = ex2(m1r - mn1);
        m0r = mn0; m1r = mn1;

        float rs0 = 0.f, rs1 = 0.f;
        #pragma unroll
        for (int nt = 0; nt < 8; nt++) {
            s[nt][0] = ex2(s[nt][0] - mn0);
            s[nt][1] = ex2(s[nt][1] - mn0);
            s[nt][2] = ex2(s[nt][2] - mn1);
            s[nt][3] = ex2(s[nt][3] - mn1);
            rs0 += s[nt][0] + s[nt][1];
            rs1 += s[nt][2] + s[nt][3];
        }
        l0 = l0 * cr0 + rs0;
        l1 = l1 * cr1 + rs1;

        #pragma unroll
        for (int nt = 0; nt < 8; nt++) {
            o[nt][0] *= cr0; o[nt][1] *= cr0;
            o[nt][2] *= cr1; o[nt][3] *= cr1;
        }

        // --- O += P V (P and V as raw f32 bits) ---
        #pragma unroll
        for (int c8 = 0; c8 < 8; c8++) {
            uint32_t pa[4];
            pa[0] = __float_as_uint(s[c8][0]);
            pa[1] = __float_as_uint(s[c8][2]);
            pa[2] = __float_as_uint(s[c8][1]);
            pa[3] = __float_as_uint(s[c8][3]);
            const uint32_t* vrow0 = &Vf[(c8 * 8 + tig    ) * VPAD];
            const uint32_t* vrow1 = &Vf[(c8 * 8 + tig + 4) * VPAD];
            #pragma unroll
            for (int nt = 0; nt < 8; nt++) {
                uint32_t b0 = vrow0[nt * 8 + gid];
                uint32_t b1 = vrow1[nt * 8 + gid];
                mma_tf32(o[nt], pa, b0, b1);
            }
        }
        // single barrier per tile: next iteration's top barrier orders reuse
    }

    // final l reduction across the 4 lanes of each row group
    l0 += __shfl_xor_sync(0xffffffffu, l0, 1);
    l0 += __shfl_xor_sync(0xffffffffu, l0, 2);
    l1 += __shfl_xor_sync(0xffffffffu, l1, 1);
    l1 += __shfl_xor_sync(0xffffffffu, l1, 2);

    if (nch == 1) {
        const float inv0 = 1.0f / l0;
        const float inv1 = 1.0f / l1;
        float* orow0 = &outp[((size_t)b * Tt + qr0    ) * Hh];
        float* orow1 = &outp[((size_t)b * Tt + qr0 + 8) * Hh];
        #pragma unroll
        for (int nt = 0; nt < 8; nt++) {
            *(float2*)&orow0[nt * 8 + tig * 2] =
                make_float2(o[nt][0] * inv0, o[nt][1] * inv0);
            *(float2*)&orow1[nt * 8 + tig * 2] =
                make_float2(o[nt][2] * inv1, o[nt][3] * inv1);
        }
    } else {
        const int slot = (b * 64 + qt) * 8 + ci;
        const int r0 = wid * 16 + gid;
        float* prow0 = g_pO[slot][r0];
        float* prow1 = g_pO[slot][r0 + 8];
        #pragma unroll
        for (int nt = 0; nt < 8; nt++) {
            *(float2*)&prow0[nt * 8 + tig * 2] = make_float2(o[nt][0], o[nt][1]);
            *(float2*)&prow1[nt * 8 + tig * 2] = make_float2(o[nt][2], o[nt][3]);
        }
        if (tig == 0) {
            g_pml[slot][r0    ] = make_float2(m0r, l0);
            g_pml[slot][r0 + 8] = make_float2(m1r, l1);
        }
    }
}

// ---------------------------------------------------------------------------
// Kernel 3: merge split-K partials for qt >= 8 (up to 8 chunks, log2-domain m).
// Parallelized: 2 CTAs per (b,qt) unit, 32 rows each -> 448 CTAs (~3/SM).
// Thread mapping: row = half*32 + (tid>>3), seg = tid&7 (8 floats per seg).
// ---------------------------------------------------------------------------
__global__ __launch_bounds__(256) void reduce_kernel(float* __restrict__ outp)
{
    const int b    = blockIdx.x / 112;
    const int rem  = blockIdx.x % 112;
    const int qt   = 8 + (rem >> 1);
    const int half = rem & 1;
    const int nch  = (qt >> 3) + 1;       // 2..8
    const int row  = half * 32 + (threadIdx.x >> 3);
    const int seg  = threadIdx.x & 7;     // 8 floats per segment
    const int slot0 = (b * 64 + qt) * 8;

    float m[8], w[8];
    float M = -1e30f;
    #pragma unroll
    for (int i = 0; i < 8; i++) {
        if (i < nch) { m[i] = g_pml[slot0 + i][row].x; M = fmaxf(M, m[i]); }
    }
    float L = 0.f;
    #pragma unroll
    for (int i = 0; i < 8; i++) {
        if (i < nch) {
            w[i] = ex2(m[i] - M);
            L += w[i] * g_pml[slot0 + i][row].y;
        }
    }
    const float inv = 1.0f / L;

    float* orow = &outp[((size_t)b * Tt + qt * 64 + row) * Hh + seg * 8];
    #pragma unroll
    for (int g4 = 0; g4 < 2; g4++) {
        float4 acc = make_float4(0.f, 0.f, 0.f, 0.f);
        #pragma unroll
        for (int i = 0; i < 8; i++) {
            if (i < nch) {
                float4 pv = *(const float4*)&g_pO[slot0 + i][row][seg * 8 + g4 * 4];
                acc.x += w[i] * pv.x; acc.y += w[i] * pv.y;
                acc.z += w[i] * pv.z; acc.w += w[i] * pv.w;
            }
        }
        acc.x *= inv; acc.y *= inv; acc.z *= inv; acc.w *= inv;
        *(float4*)&orow[g4 * 4] = acc;
    }
}

// ---------------------------------------------------------------------------
extern "C" void kernel_launch(void* const* d_in, const int* in_sizes, int n_in,
                              void* d_out, int out_size)
{
    const float* x    = (const float*)d_in[0];
    const float* bias = (const float*)d_in[1];
    const float* wk   = (const float*)d_in[2];
    const float* wq   = (const float*)d_in[3];
    const float* wv   = (const float*)d_in[4];
    float* out = (float*)d_out;

    const int psmem = (64 * KPAD + 64 * WPAD) * 4;       // 68608 B
    cudaFuncSetAttribute(proj_kernel,
                         cudaFuncAttributeMaxDynamicSharedMemorySize, psmem);
    proj_kernel<<<Bb * Tt / 64, 128, psmem>>>(x, wk, wq, wv);

    const int asmem = 2 * (64 * KPAD + 64 * VPAD) * 4;   // 71680 B
    cudaFuncSetAttribute(attn_kernel,
                         cudaFuncAttributeMaxDynamicSharedMemorySize, asmem);
    attn_kernel<<<4 * 288, 128, asmem>>>(bias, out);

    reduce_kernel<<<Bb * 112, 256>>>(out);
}